// round 9
// baseline (speedup 1.0000x reference)
#include <cuda_runtime.h>

#define BATCH 64
#define IN_F  512
#define OUT_F 512
#define NB    8
#define KDIM  9            // slot 0 = silu (pairs with w), 1..8 = T_k (pair with c*w)

#define O_TILE 64
#define IC     16          // i-range per CTA (split-K)
#define STEP   8           // i's staged per smem fill
#define NSPLIT (IN_F / IC) // 32

// Scratch (static device globals — no allocation)
__device__ float A_g[IN_F * KDIM * BATCH];          // [i][k][b], 1.18 MB
__device__ float P_g[NSPLIT * BATCH * OUT_F];       // split-K partials, 4 MB

// ---------------------------------------------------------------------------
// Kernel 1: basis + silu precompute. T_k via Chebyshev recurrence (== cos(k*acos(t))).
// 256 threads = 4 i's per CTA, 128 CTAs.
// ---------------------------------------------------------------------------
__global__ __launch_bounds__(256) void prep_kernel(const float* __restrict__ x) {
    int i = blockIdx.x * 4 + (threadIdx.x >> 6); // 0..511
    int b = threadIdx.x & 63;                    // 0..63
    float xv = x[b * IN_F + i];
    float t = tanhf(xv);
    const float lim = 1.0f - 1e-6f;
    t = fminf(fmaxf(t, -lim), lim);
    float sil = xv / (1.0f + expf(-xv));

    float* dst = A_g + i * (KDIM * BATCH) + b;
    dst[0] = sil;
    float tkm1 = 1.0f;
    float tk = t;
    dst[BATCH] = t;
#pragma unroll
    for (int k = 2; k <= NB; ++k) {
        float tn = 2.0f * t * tk - tkm1;
        dst[k * BATCH] = tn;
        tkm1 = tk;
        tk = tn;
    }
}

// ---------------------------------------------------------------------------
// Packed f32x2 helpers (FFMA2 path — not reachable from plain C++)
// ---------------------------------------------------------------------------
__device__ __forceinline__ unsigned long long rep2(float v) {
    unsigned long long r;
    asm("mov.b64 %0, {%1, %1};" : "=l"(r) : "f"(v));
    return r;
}
__device__ __forceinline__ void fma2(unsigned long long& d,
                                     unsigned long long a,
                                     unsigned long long b) {
    asm("fma.rn.f32x2 %0, %1, %2, %0;" : "+l"(d) : "l"(a), "l"(b));
}
__device__ __forceinline__ float2 unpk(unsigned long long v) {
    float2 f;
    asm("mov.b64 {%0, %1}, %2;" : "=f"(f.x), "=f"(f.y) : "l"(v));
    return f;
}

// ---------------------------------------------------------------------------
// Kernel 2: out_partial = A (64 x 4608) * B (4608 x O_TILE), B = [w ; c*w] on the fly.
// Grid: (OUT_F/O_TILE = 8, IN_F/IC = 32) = 256 CTAs, 256 threads.
// Thread micro-tile: 4 batch-pairs (f32x2) x 2 outputs = 8 f32x2 accumulators.
// ---------------------------------------------------------------------------
__global__ __launch_bounds__(256) void gemm_kernel(const float* __restrict__ w,
                                                   const float* __restrict__ c) {
    __shared__ float sA[STEP][KDIM][BATCH];    // 18 KB
    __shared__ float sCW[STEP][KDIM][O_TILE];  // 18 KB

    const int tid  = threadIdx.x;
    const int o0   = blockIdx.x * O_TILE;
    const int i0   = blockIdx.y * IC;
    const int t_og = tid & 31;   // output pair group: o_local = 2*t_og
    const int t_bg = tid >> 5;   // == warp id: batch base = 8*t_bg (broadcast LDS)

    unsigned long long acc[2][4];
#pragma unroll
    for (int oo = 0; oo < 2; ++oo)
#pragma unroll
        for (int bp = 0; bp < 4; ++bp) acc[oo][bp] = 0ull;

    for (int st = 0; st < IC / STEP; ++st) {
        const int ib = i0 + st * STEP;

        // Stage A tile: contiguous region of A_g, float4 copy.
        {
            const float4* srcA = (const float4*)(A_g + ib * (KDIM * BATCH));
            float4* dA = (float4*)sA;
            for (int idx = tid; idx < STEP * KDIM * BATCH / 4; idx += 256)
                dA[idx] = srcA[idx];
        }
        // Stage CW tile: cw[ii][0][o] = w, cw[ii][1+j][o] = c[i][o][j] * w.
        for (int p = tid; p < STEP * O_TILE; p += 256) {
            const int ii = p >> 6;
            const int ol = p & 63;
            const int io = (ib + ii) * OUT_F + (o0 + ol);
            const float wv = w[io];
            const float4* cp = (const float4*)(c + (size_t)io * NB);
            const float4 c0 = cp[0];
            const float4 c1 = cp[1];
            sCW[ii][0][ol] = wv;
            sCW[ii][1][ol] = c0.x * wv;
            sCW[ii][2][ol] = c0.y * wv;
            sCW[ii][3][ol] = c0.z * wv;
            sCW[ii][4][ol] = c0.w * wv;
            sCW[ii][5][ol] = c1.x * wv;
            sCW[ii][6][ol] = c1.y * wv;
            sCW[ii][7][ol] = c1.z * wv;
            sCW[ii][8][ol] = c1.w * wv;
        }
        __syncthreads();

#pragma unroll
        for (int ii = 0; ii < STEP; ++ii) {
#pragma unroll
            for (int k = 0; k < KDIM; ++k) {
                // A: warp-uniform address -> smem broadcast, conflict-free.
                ulonglong2 A0 = *(const ulonglong2*)&sA[ii][k][8 * t_bg];
                ulonglong2 A1 = *(const ulonglong2*)&sA[ii][k][8 * t_bg + 4];
                // CW: 8B stride across lanes, conflict-free.
                float2 cw = *(const float2*)&sCW[ii][k][2 * t_og];
                unsigned long long cx = rep2(cw.x);
                unsigned long long cy = rep2(cw.y);
                // Interleave the two output chains: no back-to-back writes to
                // the same accumulator, 8 independent FFMA2 chains in flight.
                fma2(acc[0][0], A0.x, cx);
                fma2(acc[1][0], A0.x, cy);
                fma2(acc[0][1], A0.y, cx);
                fma2(acc[1][1], A0.y, cy);
                fma2(acc[0][2], A1.x, cx);
                fma2(acc[1][2], A1.x, cy);
                fma2(acc[0][3], A1.y, cx);
                fma2(acc[1][3], A1.y, cy);
            }
        }
        __syncthreads();
    }

    // Epilogue: plain stores of split-K partials (disjoint per blockIdx.y).
    float* P = P_g + blockIdx.y * (BATCH * OUT_F);
#pragma unroll
    for (int oo = 0; oo < 2; ++oo) {
#pragma unroll
        for (int bp = 0; bp < 4; ++bp) {
            float2 v = unpk(acc[oo][bp]);
            const int o = o0 + 2 * t_og + oo;
            const int b = 8 * t_bg + 2 * bp;
            P[b * OUT_F + o]       = v.x;
            P[(b + 1) * OUT_F + o] = v.y;
        }
    }
}

// ---------------------------------------------------------------------------
// Kernel 3: split-K reduction (also overwrites the poisoned output).
// ---------------------------------------------------------------------------
__global__ void reduce_kernel(float* __restrict__ out) {
    const int j = blockIdx.x * blockDim.x + threadIdx.x;
    float s = 0.0f;
#pragma unroll
    for (int p = 0; p < NSPLIT; ++p) s += P_g[p * (BATCH * OUT_F) + j];
    out[j] = s;
}

// ---------------------------------------------------------------------------
extern "C" void kernel_launch(void* const* d_in, const int* in_sizes, int n_in,
                              void* d_out, int out_size) {
    const float* x = (const float*)d_in[0];  // (64, 512)
    const float* w = (const float*)d_in[1];  // (512, 512)
    const float* c = (const float*)d_in[2];  // (512, 512, 8)
    float* out = (float*)d_out;              // (64, 512)

    prep_kernel<<<IN_F / 4, 256>>>(x);
    gemm_kernel<<<dim3(OUT_F / O_TILE, IN_F / IC), 256>>>(w, c);
    reduce_kernel<<<(BATCH * OUT_F) / 256, 256>>>(out);
}

// round 10
// speedup vs baseline: 1.0231x; 1.0231x over previous
#include <cuda_runtime.h>

#define BATCH 64
#define IN_F  512
#define OUT_F 512
#define NB    8
#define KDIM  9            // slot 0 = silu (pairs with w), 1..8 = T_k (pair with c*w)

#define O_TILE 64
#define IC     16          // i-range per CTA (split-K)
#define STEP   8           // i's staged per smem fill
#define NSPLIT (IN_F / IC) // 32

// Scratch (static device globals — no allocation)
__device__ float A_g[IN_F * KDIM * BATCH];          // [i][k][b], 1.18 MB
__device__ float P_g[NSPLIT * BATCH * OUT_F];       // split-K partials, 4 MB

// ---------------------------------------------------------------------------
// Kernel 1: basis + silu precompute.
// R10 fix: coalesced x loads (lane-fast index = i, 4 consecutive floats per
// b-row per 4-lane group) and silu via the exact identity
// silu(x) = x * 0.5 * (1 + tanh(x/2))  -> 2 MUFU.TANH per point, no exp/div.
// Grid 128 x 256: thread handles one (b, i) point.
// ---------------------------------------------------------------------------
__global__ __launch_bounds__(256) void prep_kernel(const float* __restrict__ x) {
    const int t = threadIdx.x;
    const int b = t >> 2;                    // 0..63
    const int i = blockIdx.x * 4 + (t & 3);  // 0..511
    // Warp footprint: 8 b-rows x 16B contiguous -> fully-used sectors.
    float xv = x[b * IN_F + i];

    float tt = tanhf(xv);
    const float lim = 1.0f - 1e-6f;
    tt = fminf(fmaxf(tt, -lim), lim);
    // silu(x) = x * sigmoid(x), sigmoid(x) = 0.5*(1 + tanh(x/2)) (exact)
    float sil = xv * 0.5f * (1.0f + tanhf(0.5f * xv));

    float* dst = A_g + i * (KDIM * BATCH) + b;
    dst[0] = sil;
    float tkm1 = 1.0f;
    float tk = tt;
    dst[BATCH] = tt;
#pragma unroll
    for (int k = 2; k <= NB; ++k) {
        float tn = 2.0f * tt * tk - tkm1;
        dst[k * BATCH] = tn;
        tkm1 = tk;
        tk = tn;
    }
}

// ---------------------------------------------------------------------------
// Packed f32x2 helpers (FFMA2 path — not reachable from plain C++)
// ---------------------------------------------------------------------------
__device__ __forceinline__ unsigned long long rep2(float v) {
    unsigned long long r;
    asm("mov.b64 %0, {%1, %1};" : "=l"(r) : "f"(v));
    return r;
}
__device__ __forceinline__ void fma2(unsigned long long& d,
                                     unsigned long long a,
                                     unsigned long long b) {
    asm("fma.rn.f32x2 %0, %1, %2, %0;" : "+l"(d) : "l"(a), "l"(b));
}
__device__ __forceinline__ float2 unpk(unsigned long long v) {
    float2 f;
    asm("mov.b64 {%0, %1}, %2;" : "=f"(f.x), "=f"(f.y) : "l"(v));
    return f;
}

// ---------------------------------------------------------------------------
// Kernel 2: out_partial = A (64 x 4608) * B (4608 x O_TILE), B = [w ; c*w] on the fly.
// Grid: (OUT_F/O_TILE = 8, IN_F/IC = 32) = 256 CTAs, 256 threads.
// Thread micro-tile: 4 batch-pairs (f32x2) x 2 outputs = 8 f32x2 accumulators.
// ---------------------------------------------------------------------------
__global__ __launch_bounds__(256) void gemm_kernel(const float* __restrict__ w,
                                                   const float* __restrict__ c) {
    __shared__ float sA[STEP][KDIM][BATCH];    // 18 KB
    __shared__ float sCW[STEP][KDIM][O_TILE];  // 18 KB

    const int tid  = threadIdx.x;
    const int o0   = blockIdx.x * O_TILE;
    const int i0   = blockIdx.y * IC;
    const int t_og = tid & 31;   // output pair group: o_local = 2*t_og
    const int t_bg = tid >> 5;   // == warp id: batch base = 8*t_bg (broadcast LDS)

    unsigned long long acc[2][4];
#pragma unroll
    for (int oo = 0; oo < 2; ++oo)
#pragma unroll
        for (int bp = 0; bp < 4; ++bp) acc[oo][bp] = 0ull;

    for (int st = 0; st < IC / STEP; ++st) {
        const int ib = i0 + st * STEP;

        // Stage A tile: contiguous region of A_g, float4 copy.
        {
            const float4* srcA = (const float4*)(A_g + ib * (KDIM * BATCH));
            float4* dA = (float4*)sA;
            for (int idx = tid; idx < STEP * KDIM * BATCH / 4; idx += 256)
                dA[idx] = srcA[idx];
        }
        // Stage CW tile: cw[ii][0][o] = w, cw[ii][1+j][o] = c[i][o][j] * w.
        for (int p = tid; p < STEP * O_TILE; p += 256) {
            const int ii = p >> 6;
            const int ol = p & 63;
            const int io = (ib + ii) * OUT_F + (o0 + ol);
            const float wv = w[io];
            const float4* cp = (const float4*)(c + (size_t)io * NB);
            const float4 c0 = cp[0];
            const float4 c1 = cp[1];
            sCW[ii][0][ol] = wv;
            sCW[ii][1][ol] = c0.x * wv;
            sCW[ii][2][ol] = c0.y * wv;
            sCW[ii][3][ol] = c0.z * wv;
            sCW[ii][4][ol] = c0.w * wv;
            sCW[ii][5][ol] = c1.x * wv;
            sCW[ii][6][ol] = c1.y * wv;
            sCW[ii][7][ol] = c1.z * wv;
            sCW[ii][8][ol] = c1.w * wv;
        }
        __syncthreads();

#pragma unroll
        for (int ii = 0; ii < STEP; ++ii) {
#pragma unroll
            for (int k = 0; k < KDIM; ++k) {
                // A: warp-uniform address -> smem broadcast, conflict-free.
                ulonglong2 A0 = *(const ulonglong2*)&sA[ii][k][8 * t_bg];
                ulonglong2 A1 = *(const ulonglong2*)&sA[ii][k][8 * t_bg + 4];
                // CW: 8B stride across lanes, conflict-free.
                float2 cw = *(const float2*)&sCW[ii][k][2 * t_og];
                unsigned long long cx = rep2(cw.x);
                unsigned long long cy = rep2(cw.y);
                // Interleave the two output chains: no back-to-back writes to
                // the same accumulator, 8 independent FFMA2 chains in flight.
                fma2(acc[0][0], A0.x, cx);
                fma2(acc[1][0], A0.x, cy);
                fma2(acc[0][1], A0.y, cx);
                fma2(acc[1][1], A0.y, cy);
                fma2(acc[0][2], A1.x, cx);
                fma2(acc[1][2], A1.x, cy);
                fma2(acc[0][3], A1.y, cx);
                fma2(acc[1][3], A1.y, cy);
            }
        }
        __syncthreads();
    }

    // Epilogue: plain stores of split-K partials (disjoint per blockIdx.y).
    float* P = P_g + blockIdx.y * (BATCH * OUT_F);
#pragma unroll
    for (int oo = 0; oo < 2; ++oo) {
#pragma unroll
        for (int bp = 0; bp < 4; ++bp) {
            float2 v = unpk(acc[oo][bp]);
            const int o = o0 + 2 * t_og + oo;
            const int b = 8 * t_bg + 2 * bp;
            P[b * OUT_F + o]       = v.x;
            P[(b + 1) * OUT_F + o] = v.y;
        }
    }
}

// ---------------------------------------------------------------------------
// Kernel 3: split-K reduction (also overwrites the poisoned output).
// ---------------------------------------------------------------------------
__global__ void reduce_kernel(float* __restrict__ out) {
    const int j = blockIdx.x * blockDim.x + threadIdx.x;
    float s = 0.0f;
#pragma unroll
    for (int p = 0; p < NSPLIT; ++p) s += P_g[p * (BATCH * OUT_F) + j];
    out[j] = s;
}

// ---------------------------------------------------------------------------
extern "C" void kernel_launch(void* const* d_in, const int* in_sizes, int n_in,
                              void* d_out, int out_size) {
    const float* x = (const float*)d_in[0];  // (64, 512)
    const float* w = (const float*)d_in[1];  // (512, 512)
    const float* c = (const float*)d_in[2];  // (512, 512, 8)
    float* out = (float*)d_out;              // (64, 512)

    prep_kernel<<<IN_F / 4, 256>>>(x);
    gemm_kernel<<<dim3(OUT_F / O_TILE, IN_F / IC), 256>>>(w, c);
    reduce_kernel<<<(BATCH * OUT_F) / 256, 256>>>(out);
}